// round 10
// baseline (speedup 1.0000x reference)
#include <cuda_runtime.h>
#include <math.h>

#define BB 64
#define SS 1024
#define DD 1024
#define EE 8
#define KTOP 2

#define OSPLIT 32                 // o-split for W2 precompute

// wk_b geometry (R5 proven): warp = 4 token-octets, 2 tokens/lane, 8 tok/warp
#define BTHREADS 256
#define WARPS_B (BTHREADS / 32)                // 8
#define TOK_PER_WARP 8
#define BLK_TOK (WARPS_B * TOK_PER_WARP)       // 64
#define NBLOCKS_B (BB * SS / BLK_TOK)          // 1024
#define BLOCKS_PER_BATCH (SS / BLK_TOK)        // 16

#define MASK_ELEMS (BB * SS * EE)   // 524288
#define IDX_OFF    MASK_ELEMS
#define LOSS_OFF   (MASK_ELEMS + BB * KTOP)

// ---------------- scratch (device globals: no allocation allowed) ----------
__device__ float g_W2part[OSPLIT][EE][DD];   // 1 MB
__device__ float g_W2[EE * DD];              // 32 KB
__device__ float g_b2[EE];
__device__ float g_pScores[NBLOCKS_B][EE];   // per-block partial softmax sums
__device__ float g_pAux[NBLOCKS_B];          // per-block partial aux sums
__device__ float g_mask2d[BB * EE];

// ---------------- Kernel A: partial W2 = key_emb @ Wq (R5 proven) ----------
// grid (E, OSPLIT=32), block 256. thread handles 4 contiguous d's (float4).
__global__ void __launch_bounds__(256) wk_a(const float* __restrict__ Wq,
                                            const float* __restrict__ key) {
    int e  = blockIdx.x;
    int oc = blockIdx.y;
    int d  = threadIdx.x * 4;
    const float* wq = Wq + (size_t)(oc * 32) * DD + d;
    const float* ke = key + e * DD + oc * 32;
    float4 acc = make_float4(0.f, 0.f, 0.f, 0.f);
    #pragma unroll
    for (int o = 0; o < 32; o++) {
        float k  = __ldg(ke + o);
        float4 w = *(const float4*)(wq + (size_t)o * DD);
        acc.x += k * w.x; acc.y += k * w.y; acc.z += k * w.z; acc.w += k * w.w;
    }
    *(float4*)&g_W2part[oc][e][d] = acc;
}

// ------------- Kernel A2: reduce o-split partials -> W2, plus b2 (R5) ------
__global__ void __launch_bounds__(256) wk_a2(const float* __restrict__ bq,
                                             const float* __restrict__ key) {
    __shared__ float s_part[WARPS_B];
    int e = blockIdx.x;
    int tid = threadIdx.x;
    int d = tid * 4;
    float4 s = make_float4(0.f, 0.f, 0.f, 0.f);
    #pragma unroll
    for (int oc = 0; oc < OSPLIT; oc++) {
        float4 p = *(const float4*)&g_W2part[oc][e][d];
        s.x += p.x; s.y += p.y; s.z += p.z; s.w += p.w;
    }
    *(float4*)&g_W2[e * DD + d] = s;

    float4 bv = *(const float4*)(bq + d);
    float4 kv = *(const float4*)(key + e * DD + d);
    float p = bv.x * kv.x + bv.y * kv.y + bv.z * kv.z + bv.w * kv.w;
    #pragma unroll
    for (int off = 16; off > 0; off >>= 1) p += __shfl_xor_sync(0xFFFFFFFFu, p, off);
    int warp = tid >> 5, lane = tid & 31;
    if (lane == 0) s_part[warp] = p;
    __syncthreads();
    if (tid == 0) {
        float b2 = 0.f;
        #pragma unroll
        for (int w = 0; w < WARPS_B; w++) b2 += s_part[w];
        g_b2[e] = b2;
    }
}

// ---------------- Kernel B: main fused pass (R5 proven, untouched) ----------
__global__ void __launch_bounds__(BTHREADS, 5) wk_b(const float* __restrict__ x) {
    __shared__ float4 s_w2[EE * 256];            // 32 KB, [e][j]
    __shared__ float  s_b2[EE];
    __shared__ float  s_red[WARPS_B][EE];
    __shared__ float  s_aux[WARPS_B];

    const int tid = threadIdx.x;
    const float4* w2g = (const float4*)g_W2;
    #pragma unroll
    for (int i = 0; i < 8; i++) s_w2[tid + i * 256] = w2g[tid + i * 256];
    if (tid < EE) s_b2[tid] = g_b2[tid];
    __syncthreads();

    const int warp = tid >> 5, lane = tid & 31;
    const int oct  = lane >> 3;
    const int c    = lane & 7;
    const int tokBase = blockIdx.x * BLK_TOK + warp * TOK_PER_WARP;

    const float4* xg = (const float4*)x;
    const size_t base0 = (size_t)(tokBase + oct)     * 256 + c;
    const size_t base1 = (size_t)(tokBase + 4 + oct) * 256 + c;

    float acc[2][EE];
    #pragma unroll
    for (int t = 0; t < 2; t++)
        #pragma unroll
        for (int e = 0; e < EE; e++) acc[t][e] = 0.f;

    #pragma unroll 4
    for (int i = 0; i < 32; i++) {
        float4 xv0 = xg[base0 + i * 8];
        float4 xv1 = xg[base1 + i * 8];
        #pragma unroll
        for (int e = 0; e < EE; e++) {
            float4 wv = s_w2[e * 256 + i * 8 + c];
            acc[0][e] = fmaf(xv0.x, wv.x, acc[0][e]);
            acc[0][e] = fmaf(xv0.y, wv.y, acc[0][e]);
            acc[0][e] = fmaf(xv0.z, wv.z, acc[0][e]);
            acc[0][e] = fmaf(xv0.w, wv.w, acc[0][e]);
            acc[1][e] = fmaf(xv1.x, wv.x, acc[1][e]);
            acc[1][e] = fmaf(xv1.y, wv.y, acc[1][e]);
            acc[1][e] = fmaf(xv1.z, wv.z, acc[1][e]);
            acc[1][e] = fmaf(xv1.w, wv.w, acc[1][e]);
        }
    }

    // octet reduce: all 8 lanes of the octet end with the full dots
    #pragma unroll
    for (int t = 0; t < 2; t++)
        #pragma unroll
        for (int e = 0; e < EE; e++) {
            float v = acc[t][e];
            v += __shfl_xor_sync(0xFFFFFFFFu, v, 4);
            v += __shfl_xor_sync(0xFFFFFFFFu, v, 2);
            v += __shfl_xor_sync(0xFFFFFFFFu, v, 1);
            acc[t][e] = v;
        }

    // per-token softmax (redundant across octet lanes; only c==0 contributes)
    const float scale = 0.03125f;
    float b2r[EE];
    #pragma unroll
    for (int e = 0; e < EE; e++) b2r[e] = s_b2[e];

    float scoreAcc[EE];
    #pragma unroll
    for (int e = 0; e < EE; e++) scoreAcc[e] = 0.f;
    float auxAcc = 0.f;
    const float contrib = (c == 0) ? 1.0f : 0.0f;

    #pragma unroll
    for (int t = 0; t < 2; t++) {
        float z[EE];
        float m = -3.402823466e38f;
        #pragma unroll
        for (int e = 0; e < EE; e++) { z[e] = acc[t][e] + b2r[e]; m = fmaxf(m, z[e]); }
        float ex[EE];
        float denom = 0.f;
        #pragma unroll
        for (int e = 0; e < EE; e++) { ex[e] = __expf((z[e] - m) * scale); denom += ex[e]; }
        float rdenom = __frcp_rn(denom);
        #pragma unroll
        for (int e = 0; e < EE; e++) {
            float w = ex[e] * rdenom;
            scoreAcc[e] += contrib * w;
            auxAcc      += contrib * w * __logf(w + 1e-9f);
        }
    }

    // block reduce
    #pragma unroll
    for (int e = 0; e < EE; e++) {
        float v = scoreAcc[e];
        v += __shfl_xor_sync(0xFFFFFFFFu, v, 16);
        v += __shfl_xor_sync(0xFFFFFFFFu, v, 8);
        v += __shfl_xor_sync(0xFFFFFFFFu, v, 4);
        v += __shfl_xor_sync(0xFFFFFFFFu, v, 2);
        v += __shfl_xor_sync(0xFFFFFFFFu, v, 1);
        if (lane == 0) s_red[warp][e] = v;
    }
    float a = auxAcc;
    #pragma unroll
    for (int off = 16; off > 0; off >>= 1) a += __shfl_xor_sync(0xFFFFFFFFu, a, off);
    if (lane == 0) s_aux[warp] = a;
    __syncthreads();

    if (warp == 0) {
        if (lane < EE) {
            float s = 0.f;
            #pragma unroll
            for (int w2 = 0; w2 < WARPS_B; w2++) s += s_red[w2][lane];
            g_pScores[blockIdx.x][lane] = s;
        }
        if (lane == 0) {
            float s = 0.f;
            #pragma unroll
            for (int w2 = 0; w2 < WARPS_B; w2++) s += s_aux[w2];
            g_pAux[blockIdx.x] = s;
        }
    }
}

// ---------------- Kernel C: top-k, mask2d, router loss (R5 proven) ----------
__global__ void __launch_bounds__(1024) wk_c(float* __restrict__ out) {
    __shared__ float s_mask[BB * EE];
    __shared__ float s_auxw[32];
    int tid  = threadIdx.x;
    int warp = tid >> 5, lane = tid & 31;

    // aux partial: one element per thread (NBLOCKS_B == 1024)
    float a = g_pAux[tid];
    #pragma unroll
    for (int off = 16; off > 0; off >>= 1) a += __shfl_xor_sync(0xFFFFFFFFu, a, off);
    if (lane == 0) s_auxw[warp] = a;

    // scores: half-warp per batch (64 batches, 32 warps)
    int b   = tid >> 4;            // 0..63
    int sub = tid & 15;
    const float4* ps = (const float4*)g_pScores;   // [1024][2] float4
    float4 lo = ps[(b * BLOCKS_PER_BATCH + sub) * 2 + 0];
    float4 hi = ps[(b * BLOCKS_PER_BATCH + sub) * 2 + 1];
    #pragma unroll
    for (int off = 8; off > 0; off >>= 1) {
        lo.x += __shfl_xor_sync(0xFFFFFFFFu, lo.x, off);
        lo.y += __shfl_xor_sync(0xFFFFFFFFu, lo.y, off);
        lo.z += __shfl_xor_sync(0xFFFFFFFFu, lo.z, off);
        lo.w += __shfl_xor_sync(0xFFFFFFFFu, lo.w, off);
        hi.x += __shfl_xor_sync(0xFFFFFFFFu, hi.x, off);
        hi.y += __shfl_xor_sync(0xFFFFFFFFu, hi.y, off);
        hi.z += __shfl_xor_sync(0xFFFFFFFFu, hi.z, off);
        hi.w += __shfl_xor_sync(0xFFFFFFFFu, hi.w, off);
    }

    if (sub == 0) {
        float sc[EE] = {lo.x, lo.y, lo.z, lo.w, hi.x, hi.y, hi.z, hi.w};
        // top-2, ties -> lowest index first (jax.lax.top_k semantics)
        int i1 = 0; float v1 = sc[0];
        #pragma unroll
        for (int e = 1; e < EE; e++) if (sc[e] > v1) { v1 = sc[e]; i1 = e; }
        int i2 = -1; float v2 = -3.402823466e38f;
        #pragma unroll
        for (int e = 0; e < EE; e++)
            if (e != i1 && sc[e] > v2) { v2 = sc[e]; i2 = e; }
        #pragma unroll
        for (int e = 0; e < EE; e++) {
            float mv = (e == i1 || e == i2) ? 1.0f : 0.0f;
            s_mask[b * EE + e]   = mv;
            g_mask2d[b * EE + e] = mv;
        }
        out[IDX_OFF + b * KTOP + 0] = (float)i1;
        out[IDX_OFF + b * KTOP + 1] = (float)i2;
    }
    __syncthreads();

    if (warp == 0) {
        float av = s_auxw[lane];
        #pragma unroll
        for (int off = 16; off > 0; off >>= 1) av += __shfl_xor_sync(0xFFFFFFFFu, av, off);
        float aux = av / (float)(BB * SS * EE);

        float t = 0.f;
        if (lane < EE) {
            float cnt = 0.f;
            #pragma unroll 8
            for (int bb = 0; bb < BB; bb++) cnt += s_mask[bb * EE + lane];
            const float ideal = 1.0f / (float)EE;
            t = ideal * (__logf(ideal) - __logf(cnt / (float)BB));
        }
        #pragma unroll
        for (int off = 4; off > 0; off >>= 1) t += __shfl_xor_sync(0xFFFFFFFFu, t, off);
        if (lane == 0)
            out[LOSS_OFF] = 1e-3f * (t / (float)EE) + 1e-3f * aux;
    }
}

// ---------------- Kernel D: broadcast mask2d -> mask [B,S,E] ----------------
// Each thread reads its batch row once (b constant across its 4-float4 span)
// and fires 4 independent STG.128.
__global__ void __launch_bounds__(256) wk_d(float* __restrict__ out) {
    int t = blockIdx.x * blockDim.x + threadIdx.x;   // 0..32767
    int b = t >> 9;                                  // 512 threads per batch
    const float4* m = (const float4*)(g_mask2d + b * EE);
    float4 lo = m[0];
    float4 hi = m[1];
    float4* o = (float4*)out + (size_t)t * 4;
    o[0] = lo; o[1] = hi; o[2] = lo; o[3] = hi;
}

// ---------------- launch ----------------------------------------------------
extern "C" void kernel_launch(void* const* d_in, const int* in_sizes, int n_in,
                              void* d_out, int out_size) {
    const float* x   = (const float*)d_in[0];
    const float* Wq  = (const float*)d_in[1];
    const float* bq  = (const float*)d_in[2];
    const float* key = (const float*)d_in[3];
    float* out = (float*)d_out;

    wk_a<<<dim3(EE, OSPLIT), 256>>>(Wq, key);
    wk_a2<<<EE, 256>>>(bq, key);
    wk_b<<<NBLOCKS_B, BTHREADS>>>(x);
    wk_c<<<1, 1024>>>(out);
    wk_d<<<128, 256>>>(out);
}